// round 10
// baseline (speedup 1.0000x reference)
#include <cuda_runtime.h>

#define NDIMS  3
#define NCOLS  500000
#define RANKV  64
#define K1V    32
#define BATCHV 8192
#define EPB    16                         /* elements per block (8 warps x 2) */
#define NBLK   (BATCHV / EPB)             /* 512 blocks -> ~single wave */
#define NGATH  (NDIMS * BATCHV * RANKV)
#define DSTR   (BATCHV * K1V * 16)        /* eps per-dim stride in float4 */

__device__ float2       g_part[NBLK];
__device__ unsigned int g_ticket = 0;

// ---------------------------------------------------------------------------
// Fast natural log (Cephes logf polynomial, FMA-pipe only). x > 0 (normal).
// ---------------------------------------------------------------------------
__device__ __forceinline__ float fast_ln(float x) {
    int   i = __float_as_int(x);
    int   e = (i - 0x3F3504F3) >> 23;
    float m = __int_as_float(i - (e << 23));
    float z = m - 1.0f;
    float p =            7.0376836292e-2f;
    p = fmaf(p, z, -1.1514610310e-1f);
    p = fmaf(p, z,  1.1676998740e-1f);
    p = fmaf(p, z, -1.2420140846e-1f);
    p = fmaf(p, z,  1.4249322787e-1f);
    p = fmaf(p, z, -1.6668057665e-1f);
    p = fmaf(p, z,  2.0000714765e-1f);
    p = fmaf(p, z, -2.4999993993e-1f);
    p = fmaf(p, z,  3.3333331174e-1f);
    float z2 = z * z;
    float y  = p * z2 * z;
    y = fmaf(-0.5f, z2, y);
    return fmaf((float)e, 0.693147180559945f, z + y);
}

// ---------------------------------------------------------------------------
// Thread-per-MC-sample layout: one warp per batch element, lane = sample k.
// fs accumulates over rank IN-REGISTER (no shuffles, no block syncs in loop).
// m/L^2 rows staged to a per-warp smem slab once per element; uniform LDS
// broadcast in the k-loop. Warps run fully independently.
// ---------------------------------------------------------------------------
__global__ __launch_bounds__(256, 4)
void fused_k(const int*   __restrict__ entries,
             const float* __restrict__ ys,
             const float* __restrict__ means,
             const float* __restrict__ chols,
             const float* __restrict__ eps,
             float*       __restrict__ out) {
    const int t    = threadIdx.x;
    const int w    = t >> 5;
    const int lane = t & 31;

    __shared__ float4 stage[8][96];       // per warp: [6 rows][16 float4]
    __shared__ int    s_ent[EPB * 3];
    __shared__ float  s_y[EPB];

    const int b0 = blockIdx.x * EPB;
    if (t < EPB * 3) s_ent[t] = __ldg(entries + b0 * 3 + t);
    if (t < EPB)     s_y[t]   = __ldg(ys + b0 + t);
    __syncthreads();

    const float4* M4 = (const float4*)means;
    const float4* C4 = (const float4*)chols;
    const float4* E4 = (const float4*)eps;

    float lp_acc = 0.f;
    float kl_acc = 0.f;

    #pragma unroll
    for (int e = 0; e < 2; e++) {
        const int bi = w + 8 * e;
        const int b  = b0 + bi;
        const int r0 = s_ent[bi * 3 + 0];
        const int r1 = s_ent[bi * 3 + 1];
        const int r2 = s_ent[bi * 3 + 2];
        const float y = s_y[bi];

        // ---- stage gathered rows: rows 0-2 = m[d], rows 3-5 = l[d] = c^2 ----
        #pragma unroll
        for (int j = 0; j < 3; j++) {
            const int idx = j * 32 + lane;          // 0..95
            const int row = idx >> 4, col = idx & 15;
            const int d   = (row < 3) ? row : row - 3;
            const int rr  = (d == 0) ? r0 : ((d == 1) ? r1 : r2);
            const float4* bp = (row < 3) ? M4 : C4;
            float4 v = __ldg(bp + (d * NCOLS + rr) * 16 + col);
            if (row >= 3) { v.x *= v.x; v.y *= v.y; v.z *= v.z; v.w *= v.w; }
            stage[w][row * 16 + col] = v;
        }
        __syncwarp();

        // ---- k-loop: lane = sample; accumulate fs over rank in-register ----
        const float4* e0 = E4 + (0 * BATCHV + b) * 512 + lane * 16;
        const float4* e1 = e0 + DSTR;
        const float4* e2 = e1 + DSTR;
        const float4* S  = stage[w];

        float sa = 0.f, sb = 0.f;
        #pragma unroll 2
        for (int ch = 0; ch < 16; ch++) {
            // default .ca loads: the 128B line is reused by 8 consecutive ch
            const float4 a = __ldg(e0 + ch);
            const float4 q = __ldg(e1 + ch);
            const float4 c = __ldg(e2 + ch);
            const float4 m0 = S[0 * 16 + ch], m1 = S[1 * 16 + ch], m2 = S[2 * 16 + ch];
            const float4 l0 = S[3 * 16 + ch], l1 = S[4 * 16 + ch], l2 = S[5 * 16 + ch];
            float t0 = fmaf(a.x, l0.x, m0.x) * fmaf(q.x, l1.x, m1.x) * fmaf(c.x, l2.x, m2.x);
            float t1 = fmaf(a.y, l0.y, m0.y) * fmaf(q.y, l1.y, m1.y) * fmaf(c.y, l2.y, m2.y);
            float t2 = fmaf(a.z, l0.z, m0.z) * fmaf(q.z, l1.z, m1.z) * fmaf(c.z, l2.z, m2.z);
            float t3 = fmaf(a.w, l0.w, m0.w) * fmaf(q.w, l1.w, m1.w) * fmaf(c.w, l2.w, m2.w);
            if (ch & 1) sb += (t0 + t1) + (t2 + t3);
            else        sa += (t0 + t1) + (t2 + t3);
        }
        const float fs = sa + sb;
        const float dd = fs - y;
        lp_acc = fmaf(-0.5f * dd, dd, lp_acc);       // -0.5*(fs - y)^2

        // ---- KL for this element: 192 (m,l) pairs, 6 per lane, each once ----
        // kl = 0.5*(l^2 + m^2 - 1) - ln(l),  l = c^2   ("-1" folded into fin)
        const float* sf = (const float*)stage[w];
        #pragma unroll
        for (int j = 0; j < 6; j++) {
            const int p = lane + 32 * j;             // 0..191
            const int d = p >> 6, r = p & 63;
            const float mm = sf[d * 64 + r];
            const float ll = sf[(d + 3) * 64 + r];
            kl_acc += fmaf(0.5f * ll, ll, 0.5f * mm * mm) - fast_ln(ll);
        }
        __syncwarp();    // slab reads done before next element overwrites it
    }

    // ---- once-per-block reduction (only shuffles in the whole kernel) ----
    #pragma unroll
    for (int o = 16; o; o >>= 1) {
        lp_acc += __shfl_xor_sync(0xffffffffu, lp_acc, o);
        kl_acc += __shfl_xor_sync(0xffffffffu, kl_acc, o);
    }
    __shared__ float wlp[8], wkl[8];
    __shared__ bool  isLast;
    if (lane == 0) { wlp[w] = lp_acc; wkl[w] = kl_acc; }
    __syncthreads();

    if (t == 0) {
        float se = ((wlp[0] + wlp[1]) + (wlp[2] + wlp[3]))
                 + ((wlp[4] + wlp[5]) + (wlp[6] + wlp[7]));
        float sk = ((wkl[0] + wkl[1]) + (wkl[2] + wkl[3]))
                 + ((wkl[4] + wkl[5]) + (wkl[6] + wkl[7]));
        g_part[blockIdx.x] = make_float2(se, sk);
        __threadfence();
        unsigned int old = atomicAdd(&g_ticket, 1u);
        isLast = (old == (unsigned int)(gridDim.x - 1));
        if (isLast) g_ticket = 0;                    // reset for next replay
    }
    __syncthreads();

    // Last block: final reduction over all per-block partials.
    if (isLast) {
        double se = 0.0, sk = 0.0;
        for (int i = t; i < NBLK; i += 256) {
            float2 p = g_part[i];
            se += (double)p.x;
            sk += (double)p.y;
        }
        #pragma unroll
        for (int o = 16; o; o >>= 1) {
            se += __shfl_xor_sync(0xffffffffu, se, o);
            sk += __shfl_xor_sync(0xffffffffu, sk, o);
        }
        __shared__ double dse[8], dsk[8];
        if (lane == 0) { dse[w] = se; dsk[w] = sk; }
        __syncthreads();
        if (t == 0) {
            double E  = 0.0, KL = 0.0;
            #pragma unroll
            for (int i = 0; i < 8; i++) { E += dse[i]; KL += dsk[i]; }
            // E: mean over K1, minus B*K1 copies of 0.5*ln(2*pi), summed over B
            E = E / (double)K1V - (double)BATCHV * 0.91893853320467274;
            // KL: restore the "-1" per gathered element
            KL -= 0.5 * (double)NGATH;
            out[0] = (float)(-(100.0 * E - KL / (double)BATCHV));
        }
    }
}

extern "C" void kernel_launch(void* const* d_in, const int* in_sizes, int n_in,
                              void* d_out, int out_size) {
    const int*   entries = (const int*)  d_in[0];
    const float* ys      = (const float*)d_in[1];
    const float* means   = (const float*)d_in[2];
    const float* chols   = (const float*)d_in[3];
    const float* eps     = (const float*)d_in[4];

    fused_k<<<NBLK, 256>>>(entries, ys, means, chols, eps, (float*)d_out);
}

// round 11
// speedup vs baseline: 1.5075x; 1.5075x over previous
#include <cuda_runtime.h>

#define NDIMS  3
#define NCOLS  500000
#define RANKV  64
#define K1V    32
#define BATCHV 8192
#define BPB    8                          /* batch elements per block */
#define NBLK   (BATCHV / BPB)             /* 1024 blocks */
#define NGATH  (NDIMS * BATCHV * RANKV)
#define DSTR   (BATCHV * K1V * 16)        /* eps per-dim stride (float4) */
#define WSLAB  192                        /* float4 per warp per buffer   */

__device__ float2       g_part[NBLK];
__device__ unsigned int g_ticket = 0;

// ---------------------------------------------------------------------------
// Fast natural log (Cephes logf polynomial, FMA-pipe only). x > 0 (normal).
// ---------------------------------------------------------------------------
__device__ __forceinline__ float fast_ln(float x) {
    int   i = __float_as_int(x);
    int   e = (i - 0x3F3504F3) >> 23;
    float m = __int_as_float(i - (e << 23));
    float z = m - 1.0f;
    float p =            7.0376836292e-2f;
    p = fmaf(p, z, -1.1514610310e-1f);
    p = fmaf(p, z,  1.1676998740e-1f);
    p = fmaf(p, z, -1.2420140846e-1f);
    p = fmaf(p, z,  1.4249322787e-1f);
    p = fmaf(p, z, -1.6668057665e-1f);
    p = fmaf(p, z,  2.0000714765e-1f);
    p = fmaf(p, z, -2.4999993993e-1f);
    p = fmaf(p, z,  3.3333331174e-1f);
    float z2 = z * z;
    float y  = p * z2 * z;
    y = fmaf(-0.5f, z2, y);
    return fmaf((float)e, 0.693147180559945f, z + y);
}

__device__ __forceinline__ void cpa16(unsigned smem_addr, const void* gptr) {
    asm volatile("cp.async.cg.shared.global [%0], [%1], 16;"
                 :: "r"(smem_addr), "l"(gptr));
}

// ---------------------------------------------------------------------------
// R9 skeleton (coalesced half-warp-per-sample layout) + PER-WARP cp.async
// eps staging, double-buffered, one element ahead. Each lane reads back only
// smem it wrote itself -> the only sync in the loop is cp.async.wait_group.
// ---------------------------------------------------------------------------
extern __shared__ float4 ering[];   // [8 warps][2 bufs][6 slots][32 lanes]

__global__ __launch_bounds__(256, 4)
void fused_k(const int*   __restrict__ entries,
             const float* __restrict__ ys,
             const float* __restrict__ means,
             const float* __restrict__ chols,
             const float* __restrict__ eps,
             float*       __restrict__ out) {
    const int t    = threadIdx.x;
    const int w    = t >> 5;
    const int lane = t & 31;
    const int h    = lane >> 4;      // half: which k of the pair
    const int r16  = lane & 15;      // rank/4 slice

    __shared__ int   s_ent[BPB * 3];
    __shared__ float s_y[BPB];

    const int b0 = blockIdx.x * BPB;
    if (t < BPB * 3) s_ent[t] = __ldg(entries + b0 * 3 + t);
    if (t < BPB)     s_y[t]   = __ldg(ys + b0 + t);
    __syncthreads();

    const float4* M4 = (const float4*)means;
    const float4* C4 = (const float4*)chols;
    const float4* E4 = (const float4*)eps;

    // per-lane smem addresses (bytes) for this warp's two buffers
    const unsigned sb = (unsigned)__cvta_generic_to_shared(ering)
                      + (unsigned)(w * 2 * WSLAB + lane) * 16u;
    // slot s at: sb + bufsel*WSLAB*16 + s*32*16
    const int kA = 2 * w + h;        // sample of slots 0..2
    const int kB = kA + 16;          // sample of slots 3..5

    // ---- prologue: stage element 0 into buf 0 ----
    {
        const int b = b0;
        #pragma unroll
        for (int d = 0; d < 3; d++) {
            cpa16(sb + (unsigned)(d    ) * 512u, E4 + (size_t)d * DSTR + b * 512 + kA * 16 + r16);
            cpa16(sb + (unsigned)(d + 3) * 512u, E4 + (size_t)d * DSTR + b * 512 + kB * 16 + r16);
        }
        asm volatile("cp.async.commit_group;");
    }

    float lp_acc = 0.f;
    float kl_acc = 0.f;

    for (int i = 0; i < BPB; i++) {
        const int b = b0 + i;

        // ---- stage element i+1 into the other buffer (no barriers) ----
        if (i + 1 < BPB) {
            const unsigned nb = sb + (unsigned)(((i + 1) & 1) * WSLAB) * 16u;
            #pragma unroll
            for (int d = 0; d < 3; d++) {
                cpa16(nb + (unsigned)(d    ) * 512u, E4 + (size_t)d * DSTR + (b + 1) * 512 + kA * 16 + r16);
                cpa16(nb + (unsigned)(d + 3) * 512u, E4 + (size_t)d * DSTR + (b + 1) * 512 + kB * 16 + r16);
            }
            asm volatile("cp.async.commit_group;");
        }

        // ---- gathers for element i (mostly L1/L2 hits across warps) ----
        const int r0 = s_ent[i * 3 + 0];
        const int r1 = s_ent[i * 3 + 1];
        const int r2 = s_ent[i * 3 + 2];
        const int gi0 = (0 * NCOLS + r0) * 16 + r16;
        const int gi1 = (1 * NCOLS + r1) * 16 + r16;
        const int gi2 = (2 * NCOLS + r2) * 16 + r16;
        const float4 m0 = __ldg(M4 + gi0), m1 = __ldg(M4 + gi1), m2 = __ldg(M4 + gi2);
        const float y = s_y[i];
        float4 l0, l1, l2;
        {
            const float4 c0 = __ldg(C4 + gi0), c1 = __ldg(C4 + gi1), c2 = __ldg(C4 + gi2);
            l0.x = c0.x*c0.x; l0.y = c0.y*c0.y; l0.z = c0.z*c0.z; l0.w = c0.w*c0.w;
            l1.x = c1.x*c1.x; l1.y = c1.y*c1.y; l1.z = c1.z*c1.z; l1.w = c1.w*c1.w;
            l2.x = c2.x*c2.x; l2.y = c2.y*c2.y; l2.z = c2.z*c2.z; l2.w = c2.w*c2.w;
        }

        // ---- wait for element i's slab (leave i+1's group in flight) ----
        if (i + 1 < BPB) { asm volatile("cp.async.wait_group 1;" ::: "memory"); }
        else             { asm volatile("cp.async.wait_group 0;" ::: "memory"); }

        const float4* S = ering + (w * 2 + (i & 1)) * WSLAB + lane;
        const float4 eA0 = S[0 * 32], eB0 = S[1 * 32], eC0 = S[2 * 32];
        const float4 eA1 = S[3 * 32], eB1 = S[4 * 32], eC1 = S[5 * 32];

        float s0, s1;
        {
            float ax = fmaf(eA0.x, l0.x, m0.x) * fmaf(eB0.x, l1.x, m1.x) * fmaf(eC0.x, l2.x, m2.x);
            float ay = fmaf(eA0.y, l0.y, m0.y) * fmaf(eB0.y, l1.y, m1.y) * fmaf(eC0.y, l2.y, m2.y);
            float az = fmaf(eA0.z, l0.z, m0.z) * fmaf(eB0.z, l1.z, m1.z) * fmaf(eC0.z, l2.z, m2.z);
            float aw = fmaf(eA0.w, l0.w, m0.w) * fmaf(eB0.w, l1.w, m1.w) * fmaf(eC0.w, l2.w, m2.w);
            s0 = (ax + ay) + (az + aw);
        }
        {
            float ax = fmaf(eA1.x, l0.x, m0.x) * fmaf(eB1.x, l1.x, m1.x) * fmaf(eC1.x, l2.x, m2.x);
            float ay = fmaf(eA1.y, l0.y, m0.y) * fmaf(eB1.y, l1.y, m1.y) * fmaf(eC1.y, l2.y, m2.y);
            float az = fmaf(eA1.z, l0.z, m0.z) * fmaf(eB1.z, l1.z, m1.z) * fmaf(eC1.z, l2.z, m2.z);
            float aw = fmaf(eA1.w, l0.w, m0.w) * fmaf(eB1.w, l1.w, m1.w) * fmaf(eC1.w, l2.w, m2.w);
            s1 = (ax + ay) + (az + aw);
        }
        #pragma unroll
        for (int o = 1; o < 16; o <<= 1) {
            s0 += __shfl_xor_sync(0xffffffffu, s0, o);
            s1 += __shfl_xor_sync(0xffffffffu, s1, o);
        }
        if (r16 == 0) {
            float d0 = s0 - y, d1 = s1 - y;
            lp_acc = fmaf(-0.5f * d0, d0, fmaf(-0.5f * d1, d1, lp_acc));
        }

        // KL on warp 0 only; both 16-lane halves duplicate -> 0.5x at the end.
        // kl = 0.5*(l^2 + m^2 - 1) - ln(l),  l = c^2  (log(S^2) = 2*ln(c^2))
        if (w == 0) {
            float klp;
            klp = 0.5f * ( fmaf(l0.x, l0.x, m0.x*m0.x) + fmaf(l0.y, l0.y, m0.y*m0.y)
                         + fmaf(l0.z, l0.z, m0.z*m0.z) + fmaf(l0.w, l0.w, m0.w*m0.w)
                         + fmaf(l1.x, l1.x, m1.x*m1.x) + fmaf(l1.y, l1.y, m1.y*m1.y)
                         + fmaf(l1.z, l1.z, m1.z*m1.z) + fmaf(l1.w, l1.w, m1.w*m1.w)
                         + fmaf(l2.x, l2.x, m2.x*m2.x) + fmaf(l2.y, l2.y, m2.y*m2.y)
                         + fmaf(l2.z, l2.z, m2.z*m2.z) + fmaf(l2.w, l2.w, m2.w*m2.w));
            klp -= ( fast_ln(l0.x) + fast_ln(l0.y) + fast_ln(l0.z) + fast_ln(l0.w)
                   + fast_ln(l1.x) + fast_ln(l1.y) + fast_ln(l1.z) + fast_ln(l1.w)
                   + fast_ln(l2.x) + fast_ln(l2.y) + fast_ln(l2.z) + fast_ln(l2.w) );
            kl_acc += klp;
        }
    }

    // ---- once-per-block reduction ----
    #pragma unroll
    for (int o = 16; o; o >>= 1) {
        lp_acc += __shfl_xor_sync(0xffffffffu, lp_acc, o);
        kl_acc += __shfl_xor_sync(0xffffffffu, kl_acc, o);
    }
    __shared__ float wlp[8];
    __shared__ float wkl;
    __shared__ bool  isLast;
    if (lane == 0) { wlp[w] = lp_acc; if (w == 0) wkl = 0.5f * kl_acc; }
    __syncthreads();

    if (t == 0) {
        float s = ((wlp[0] + wlp[1]) + (wlp[2] + wlp[3]))
                + ((wlp[4] + wlp[5]) + (wlp[6] + wlp[7]));
        g_part[blockIdx.x] = make_float2(s, wkl);
        __threadfence();
        unsigned int old = atomicAdd(&g_ticket, 1u);
        isLast = (old == (unsigned int)(gridDim.x - 1));
        if (isLast) g_ticket = 0;
    }
    __syncthreads();

    if (isLast) {
        double se = 0.0, sk = 0.0;
        for (int i = t; i < NBLK; i += 256) {
            float2 p = g_part[i];
            se += (double)p.x;
            sk += (double)p.y;
        }
        #pragma unroll
        for (int o = 16; o; o >>= 1) {
            se += __shfl_xor_sync(0xffffffffu, se, o);
            sk += __shfl_xor_sync(0xffffffffu, sk, o);
        }
        __shared__ double dse[8], dsk[8];
        if (lane == 0) { dse[w] = se; dsk[w] = sk; }
        __syncthreads();
        if (t == 0) {
            double E  = 0.0, KL = 0.0;
            #pragma unroll
            for (int i = 0; i < 8; i++) { E += dse[i]; KL += dsk[i]; }
            E = E / (double)K1V - (double)BATCHV * 0.91893853320467274;
            KL -= 0.5 * (double)NGATH;
            out[0] = (float)(-(100.0 * E - KL / (double)BATCHV));
        }
    }
}

extern "C" void kernel_launch(void* const* d_in, const int* in_sizes, int n_in,
                              void* d_out, int out_size) {
    const int*   entries = (const int*)  d_in[0];
    const float* ys      = (const float*)d_in[1];
    const float* means   = (const float*)d_in[2];
    const float* chols   = (const float*)d_in[3];
    const float* eps     = (const float*)d_in[4];

    const int smem = 8 * 2 * WSLAB * sizeof(float4);   // 48KB dynamic ring
    static int configured = 0;
    if (!configured) {
        cudaFuncSetAttribute(fused_k, cudaFuncAttributeMaxDynamicSharedMemorySize, smem);
        configured = 1;
    }
    fused_k<<<NBLK, 256, smem>>>(entries, ys, means, chols, eps, (float*)d_out);
}

// round 12
// speedup vs baseline: 1.9728x; 1.3087x over previous
#include <cuda_runtime.h>

#define NDIMS  3
#define NCOLS  500000
#define RANKV  64
#define K1V    32
#define BATCHV 8192
#define BPB    8                          /* batch elements per block */
#define NBLK   (BATCHV / BPB)             /* 1024 blocks */
#define NGATH  (NDIMS * BATCHV * RANKV)

__device__ float2       g_part[NBLK];
__device__ unsigned int g_ticket = 0;

// ---------------------------------------------------------------------------
// Fast natural log (Cephes logf polynomial, FMA-pipe only). x > 0 (normal).
// ---------------------------------------------------------------------------
__device__ __forceinline__ float fast_ln(float x) {
    int   i = __float_as_int(x);
    int   e = (i - 0x3F3504F3) >> 23;
    float m = __int_as_float(i - (e << 23));
    float z = m - 1.0f;
    float p =            7.0376836292e-2f;
    p = fmaf(p, z, -1.1514610310e-1f);
    p = fmaf(p, z,  1.1676998740e-1f);
    p = fmaf(p, z, -1.2420140846e-1f);
    p = fmaf(p, z,  1.4249322787e-1f);
    p = fmaf(p, z, -1.6668057665e-1f);
    p = fmaf(p, z,  2.0000714765e-1f);
    p = fmaf(p, z, -2.4999993993e-1f);
    p = fmaf(p, z,  3.3333331174e-1f);
    float z2 = z * z;
    float y  = p * z2 * z;
    y = fmaf(-0.5f, z2, y);
    return fmaf((float)e, 0.693147180559945f, z + y);
}

__device__ __forceinline__ void pfL2(const void* p) {
    asm volatile("prefetch.global.L2 [%0];" :: "l"(p));
}

// ---------------------------------------------------------------------------
// R9 skeleton (best: 43.1us): 1024 blocks x 256 thr, 8 elements per block,
// half-warp (16 lanes x float4 = rank 64), 2 MC samples per warp per element.
// NEW: zero-register L2 prefetch of element i+1's eps slots + gather rows
// while computing element i — shrinks the exposed DRAM latency to L2 latency
// on every iteration after the first.
// ---------------------------------------------------------------------------
__global__ __launch_bounds__(256, 4)
void fused_k(const int*   __restrict__ entries,
             const float* __restrict__ ys,
             const float* __restrict__ means,
             const float* __restrict__ chols,
             const float* __restrict__ eps,
             float*       __restrict__ out) {
    const int t    = threadIdx.x;
    const int w    = t >> 5;
    const int lane = t & 31;
    const int h    = lane >> 4;      // half: which k of the pair
    const int r16  = lane & 15;      // rank/4 slice index

    __shared__ int   s_ent[BPB * 3];
    __shared__ float s_y[BPB];

    const int b0 = blockIdx.x * BPB;
    if (t < BPB * 3) s_ent[t] = __ldg(entries + b0 * 3 + t);
    if (t < BPB)     s_y[t]   = __ldg(ys + b0 + t);
    __syncthreads();

    const float4* M4 = (const float4*)means;
    const float4* C4 = (const float4*)chols;
    const float4* E4 = (const float4*)eps;
    const int dstride = BATCHV * K1V * 16;            // per-dim stride (float4)
    const int k0 = 2 * w + h;
    const int k1 = k0 + 16;

    float lp_acc = 0.f;
    float kl_acc = 0.f;

    #pragma unroll 2
    for (int i = 0; i < BPB; i++) {
        const int b = b0 + i;

        // ---- prefetch element i+1 into L2 (zero registers, no sync) ----
        if (i + 1 < BPB && (r16 & 7) == 0) {
            const int nbase = (b + 1) * K1V * 16 + r16;
            pfL2(E4 + nbase + k0 * 16);
            pfL2(E4 + nbase + k0 * 16 + dstride);
            pfL2(E4 + nbase + k0 * 16 + 2 * dstride);
            pfL2(E4 + nbase + k1 * 16);
            pfL2(E4 + nbase + k1 * 16 + dstride);
            pfL2(E4 + nbase + k1 * 16 + 2 * dstride);
            if (w == 0) {   // gather rows for i+1 (shared by all warps)
                const int q0 = s_ent[(i + 1) * 3 + 0];
                const int q1 = s_ent[(i + 1) * 3 + 1];
                const int q2 = s_ent[(i + 1) * 3 + 2];
                pfL2(M4 + (0 * NCOLS + q0) * 16 + r16);
                pfL2(M4 + (1 * NCOLS + q1) * 16 + r16);
                pfL2(M4 + (2 * NCOLS + q2) * 16 + r16);
                pfL2(C4 + (0 * NCOLS + q0) * 16 + r16);
                pfL2(C4 + (1 * NCOLS + q1) * 16 + r16);
                pfL2(C4 + (2 * NCOLS + q2) * 16 + r16);
            }
        }

        // ---- loads for element i ----
        const int r0 = s_ent[i * 3 + 0];
        const int r1 = s_ent[i * 3 + 1];
        const int r2 = s_ent[i * 3 + 2];
        const int gi0 = (0 * NCOLS + r0) * 16 + r16;
        const int gi1 = (1 * NCOLS + r1) * 16 + r16;
        const int gi2 = (2 * NCOLS + r2) * 16 + r16;

        const int base = b * K1V * 16 + r16;
        const float4 eA0 = __ldcs(E4 + base + k0 * 16);
        const float4 eB0 = __ldcs(E4 + base + k0 * 16 + dstride);
        const float4 eC0 = __ldcs(E4 + base + k0 * 16 + 2 * dstride);
        const float4 eA1 = __ldcs(E4 + base + k1 * 16);
        const float4 eB1 = __ldcs(E4 + base + k1 * 16 + dstride);
        const float4 eC1 = __ldcs(E4 + base + k1 * 16 + 2 * dstride);

        const float4 m0 = __ldg(M4 + gi0), m1 = __ldg(M4 + gi1), m2 = __ldg(M4 + gi2);
        const float y = s_y[i];

        // S = L^2; 'c' values die immediately after these squares.
        float4 l0, l1, l2;
        {
            const float4 c0 = __ldg(C4 + gi0), c1 = __ldg(C4 + gi1), c2 = __ldg(C4 + gi2);
            l0.x = c0.x*c0.x; l0.y = c0.y*c0.y; l0.z = c0.z*c0.z; l0.w = c0.w*c0.w;
            l1.x = c1.x*c1.x; l1.y = c1.y*c1.y; l1.z = c1.z*c1.z; l1.w = c1.w*c1.w;
            l2.x = c2.x*c2.x; l2.y = c2.y*c2.y; l2.z = c2.z*c2.z; l2.w = c2.w*c2.w;
        }

        float s0, s1;
        {
            float ax = fmaf(eA0.x, l0.x, m0.x) * fmaf(eB0.x, l1.x, m1.x) * fmaf(eC0.x, l2.x, m2.x);
            float ay = fmaf(eA0.y, l0.y, m0.y) * fmaf(eB0.y, l1.y, m1.y) * fmaf(eC0.y, l2.y, m2.y);
            float az = fmaf(eA0.z, l0.z, m0.z) * fmaf(eB0.z, l1.z, m1.z) * fmaf(eC0.z, l2.z, m2.z);
            float aw = fmaf(eA0.w, l0.w, m0.w) * fmaf(eB0.w, l1.w, m1.w) * fmaf(eC0.w, l2.w, m2.w);
            s0 = (ax + ay) + (az + aw);
        }
        {
            float ax = fmaf(eA1.x, l0.x, m0.x) * fmaf(eB1.x, l1.x, m1.x) * fmaf(eC1.x, l2.x, m2.x);
            float ay = fmaf(eA1.y, l0.y, m0.y) * fmaf(eB1.y, l1.y, m1.y) * fmaf(eC1.y, l2.y, m2.y);
            float az = fmaf(eA1.z, l0.z, m0.z) * fmaf(eB1.z, l1.z, m1.z) * fmaf(eC1.z, l2.z, m2.z);
            float aw = fmaf(eA1.w, l0.w, m0.w) * fmaf(eB1.w, l1.w, m1.w) * fmaf(eC1.w, l2.w, m2.w);
            s1 = (ax + ay) + (az + aw);
        }
        // Reduce over rank within each 16-lane group; both chains run with ILP.
        #pragma unroll
        for (int o = 1; o < 16; o <<= 1) {
            s0 += __shfl_xor_sync(0xffffffffu, s0, o);
            s1 += __shfl_xor_sync(0xffffffffu, s1, o);
        }
        if (r16 == 0) {
            float d0 = s0 - y, d1 = s1 - y;
            lp_acc = fmaf(-0.5f * d0, d0, fmaf(-0.5f * d1, d1, lp_acc));
        }

        // KL on warp 0 only; both 16-lane halves duplicate -> 0.5x at the end.
        // kl = 0.5*(l^2 + m^2 - 1) - ln(l),  l = c^2  (log(S^2) = 2*ln(c^2))
        if (w == 0) {
            float klp;
            klp = 0.5f * ( fmaf(l0.x, l0.x, m0.x*m0.x) + fmaf(l0.y, l0.y, m0.y*m0.y)
                         + fmaf(l0.z, l0.z, m0.z*m0.z) + fmaf(l0.w, l0.w, m0.w*m0.w)
                         + fmaf(l1.x, l1.x, m1.x*m1.x) + fmaf(l1.y, l1.y, m1.y*m1.y)
                         + fmaf(l1.z, l1.z, m1.z*m1.z) + fmaf(l1.w, l1.w, m1.w*m1.w)
                         + fmaf(l2.x, l2.x, m2.x*m2.x) + fmaf(l2.y, l2.y, m2.y*m2.y)
                         + fmaf(l2.z, l2.z, m2.z*m2.z) + fmaf(l2.w, l2.w, m2.w*m2.w));
            klp -= ( fast_ln(l0.x) + fast_ln(l0.y) + fast_ln(l0.z) + fast_ln(l0.w)
                   + fast_ln(l1.x) + fast_ln(l1.y) + fast_ln(l1.z) + fast_ln(l1.w)
                   + fast_ln(l2.x) + fast_ln(l2.y) + fast_ln(l2.z) + fast_ln(l2.w) );
            kl_acc += klp;
        }
    }

    // ---- once-per-block reduction ----
    #pragma unroll
    for (int o = 16; o; o >>= 1) {
        lp_acc += __shfl_xor_sync(0xffffffffu, lp_acc, o);
        kl_acc += __shfl_xor_sync(0xffffffffu, kl_acc, o);
    }
    __shared__ float wlp[8];
    __shared__ float wkl;
    __shared__ bool  isLast;
    if (lane == 0) { wlp[w] = lp_acc; if (w == 0) wkl = 0.5f * kl_acc; }
    __syncthreads();

    if (t == 0) {
        float s = ((wlp[0] + wlp[1]) + (wlp[2] + wlp[3]))
                + ((wlp[4] + wlp[5]) + (wlp[6] + wlp[7]));
        g_part[blockIdx.x] = make_float2(s, wkl);
        __threadfence();
        unsigned int old = atomicAdd(&g_ticket, 1u);
        isLast = (old == (unsigned int)(gridDim.x - 1));
        if (isLast) g_ticket = 0;                    // reset for next replay
    }
    __syncthreads();

    // Last block: final reduction over all per-block partials.
    if (isLast) {
        double se = 0.0, sk = 0.0;
        for (int i = t; i < NBLK; i += 256) {
            float2 p = g_part[i];
            se += (double)p.x;
            sk += (double)p.y;
        }
        #pragma unroll
        for (int o = 16; o; o >>= 1) {
            se += __shfl_xor_sync(0xffffffffu, se, o);
            sk += __shfl_xor_sync(0xffffffffu, sk, o);
        }
        __shared__ double dse[8], dsk[8];
        if (lane == 0) { dse[w] = se; dsk[w] = sk; }
        __syncthreads();
        if (t == 0) {
            double E  = 0.0, KL = 0.0;
            #pragma unroll
            for (int i = 0; i < 8; i++) { E += dse[i]; KL += dsk[i]; }
            E = E / (double)K1V - (double)BATCHV * 0.91893853320467274;
            KL -= 0.5 * (double)NGATH;
            out[0] = (float)(-(100.0 * E - KL / (double)BATCHV));
        }
    }
}

extern "C" void kernel_launch(void* const* d_in, const int* in_sizes, int n_in,
                              void* d_out, int out_size) {
    const int*   entries = (const int*)  d_in[0];
    const float* ys      = (const float*)d_in[1];
    const float* means   = (const float*)d_in[2];
    const float* chols   = (const float*)d_in[3];
    const float* eps     = (const float*)d_in[4];

    fused_k<<<NBLK, 256>>>(entries, ys, means, chols, eps, (float*)d_out);
}